// round 3
// baseline (speedup 1.0000x reference)
#include <cuda_runtime.h>
#include <cuda_bf16.h>
#include <math.h>

#define NN 100000
#define EG 600000
#define EE 600000

// ---------------- scratch (static device globals; no allocation) ----------------
__device__ float g_h[NN * 64];
__device__ float g_x[NN * 64];
__device__ float g_out[NN * 64];
__device__ float g_as[NN];
__device__ float g_ad[NN];
__device__ unsigned g_amax_key[NN];
__device__ float g_amaxf[NN];
__device__ float g_denom[NN];
__device__ float g_alpha[EG];
__device__ float g_Y[(size_t)NN * 1040];

__global__ void zero_scratch() {
    int i = blockIdx.x * blockDim.x + threadIdx.x;
    if (i < NN * 64) g_out[i] = 0.0f;
    if (i < NN) { g_denom[i] = 0.0f; g_amax_key[i] = 0u; }
}

// h = x @ W ; a_s = sum(h*att_s) ; a_d = sum(h*att_d)
// FIRST=true: read pos (dim 3) from xin ; FIRST=false: read g_x (dim 64)
template <bool FIRST>
__global__ void node_transform(const float* __restrict__ xin,
                               const float* __restrict__ W,
                               const float* __restrict__ att_s,
                               const float* __restrict__ att_d) {
    const int IN = FIRST ? 3 : 64;
    __shared__ float Ws[64 * 64];
    __shared__ float xs[4][64];
    __shared__ float red_s[4][2];
    __shared__ float red_d[4][2];
    int tid = threadIdx.x; // 256
    for (int i = tid; i < IN * 64; i += 256) Ws[i] = W[i];
    int node0 = blockIdx.x * 4;
    for (int i = tid; i < 4 * IN; i += 256) {
        int g = i / IN, k = i % IN;
        int n = node0 + g;
        const float* src = FIRST ? xin : g_x;
        xs[g][k] = (n < NN) ? src[(size_t)n * IN + k] : 0.0f;
    }
    __syncthreads();
    int c = tid & 63;
    int g = tid >> 6;
    int n = node0 + g;
    float v = 0.0f;
#pragma unroll
    for (int k = 0; k < IN; k++) v += xs[g][k] * Ws[k * 64 + c];
    float ps = v * att_s[c];
    float pd = v * att_d[c];
#pragma unroll
    for (int o = 16; o; o >>= 1) {
        ps += __shfl_down_sync(0xFFFFFFFFu, ps, o);
        pd += __shfl_down_sync(0xFFFFFFFFu, pd, o);
    }
    if ((tid & 31) == 0) { red_s[g][c >> 5] = ps; red_d[g][c >> 5] = pd; }
    if (n < NN) g_h[(size_t)n * 64 + c] = v;
    __syncthreads();
    if (n < NN && c == 0) {
        g_as[n] = red_s[g][0] + red_s[g][1];
        g_ad[n] = red_d[g][0] + red_d[g][1];
    }
}

__device__ __forceinline__ unsigned float_key(float f) {
    unsigned u = __float_as_uint(f);
    return (u & 0x80000000u) ? ~u : (u | 0x80000000u);
}

__global__ void edge_alpha_max(const int* __restrict__ gsrc, const int* __restrict__ gdst) {
    int i = blockIdx.x * blockDim.x + threadIdx.x;
    if (i >= EG) return;
    float a = g_as[gsrc[i]] + g_ad[gdst[i]];
    a = (a >= 0.0f) ? a : 0.2f * a;
    g_alpha[i] = a;
    atomicMax(&g_amax_key[gdst[i]], float_key(a));
}

__global__ void decode_amax() {
    int n = blockIdx.x * blockDim.x + threadIdx.x;
    if (n >= NN) return;
    unsigned k = g_amax_key[n];
    float m;
    if (k == 0u) m = 0.0f;
    else m = (k & 0x80000000u) ? __uint_as_float(k ^ 0x80000000u) : __uint_as_float(~k);
    g_amaxf[n] = m;
}

__global__ void edge_exp_denom(const int* __restrict__ gdst) {
    int i = blockIdx.x * blockDim.x + threadIdx.x;
    if (i >= EG) return;
    int d = gdst[i];
    float e = expf(g_alpha[i] - g_amaxf[d]);
    g_alpha[i] = e;
    atomicAdd(&g_denom[d], e);
}

__global__ void edge_scatter(const int* __restrict__ gsrc, const int* __restrict__ gdst) {
    int gw = (blockIdx.x * blockDim.x + threadIdx.x) >> 5;
    if (gw >= EG) return;
    int lane = threadIdx.x & 31;
    int s = gsrc[gw], d = gdst[gw];
    float w = g_alpha[gw] / (g_denom[d] + 1e-16f);
    const float* hs = g_h + (size_t)s * 64;
    float* od = g_out + (size_t)d * 64;
    atomicAdd(&od[lane],      hs[lane] * w);
    atomicAdd(&od[lane + 32], hs[lane + 32] * w);
}

__global__ void finalize_node(const float* __restrict__ bias) {
    int i = blockIdx.x * blockDim.x + threadIdx.x;
    if (i >= NN * 64) return;
    float v = g_out[i] + bias[i & 63];
    g_x[i] = (v > 0.0f) ? v : expm1f(v);
}

__global__ void gemm_y(const float* __restrict__ Wm1) {
    __shared__ float As[64][65];
    __shared__ float Bs[64][65];
    int bm = blockIdx.y, bn = blockIdx.x;
    int tid = threadIdx.x;
    for (int i = tid; i < 64 * 64; i += 256) {
        int r = i >> 6, k = i & 63;
        int m = bm * 64 + r;
        As[r][k] = (m < NN) ? g_x[(size_t)m * 64 + k] : 0.0f;
    }
    for (int i = tid; i < 64 * 64; i += 256) {
        int k = i >> 6, nl = i & 63;
        int n = bn * 64 + nl;
        float b = 0.0f;
        if (n < 1040) b = (n < 520) ? Wm1[k * 520 + n] : Wm1[(64 + k) * 520 + (n - 520)];
        Bs[k][nl] = b;
    }
    __syncthreads();
    int tx = tid & 15, ty = tid >> 4;
    float acc[4][4] = {};
#pragma unroll
    for (int k = 0; k < 64; k++) {
        float a[4], b[4];
#pragma unroll
        for (int i = 0; i < 4; i++) { a[i] = As[ty * 4 + i][k]; b[i] = Bs[k][tx * 4 + i]; }
#pragma unroll
        for (int i = 0; i < 4; i++)
#pragma unroll
            for (int j = 0; j < 4; j++) acc[i][j] += a[i] * b[j];
    }
#pragma unroll
    for (int i = 0; i < 4; i++) {
        int m = bm * 64 + ty * 4 + i;
        if (m >= NN) continue;
#pragma unroll
        for (int j = 0; j < 4; j++) {
            int n = bn * 64 + tx * 4 + j;
            if (n < 1040) g_Y[(size_t)m * 1040 + n] = acc[i][j];
        }
    }
}

__global__ void edge_mlp(const int* __restrict__ esrc, const int* __restrict__ edst,
                         const float* __restrict__ ea,
                         const float* __restrict__ Wm1, const float* __restrict__ bm1,
                         const float* __restrict__ Wm2, const float* __restrict__ bm2,
                         float* __restrict__ out) {
    __shared__ float sB[520], sW2[520], sC0[520], sC1[520];
    int tid = threadIdx.x;
    for (int i = tid; i < 520; i += 256) {
        sB[i] = bm1[i];
        sW2[i] = Wm2[i];
        sC0[i] = Wm1[128 * 520 + i];
        sC1[i] = Wm1[129 * 520 + i];
    }
    __syncthreads();
    int e = (blockIdx.x * blockDim.x + tid) >> 5;
    if (e >= EE) return;
    int lane = tid & 31;
    int s = esrc[e], d = edst[e];
    float a0 = ea[2 * e], a1 = ea[2 * e + 1];
    const float* ys = g_Y + (size_t)s * 1040;
    const float* yd = g_Y + (size_t)d * 1040 + 520;
    float acc = 0.0f;
    for (int k = lane; k < 520; k += 32) {
        float v = ys[k] + yd[k] + sB[k] + a0 * sC0[k] + a1 * sC1[k];
        v = (v > 0.0f) ? v : expm1f(v);
        acc += v * sW2[k];
    }
#pragma unroll
    for (int o = 16; o; o >>= 1) acc += __shfl_down_sync(0xFFFFFFFFu, acc, o);
    if (lane == 0) out[e] = acc + bm2[0];
}

static void run_gat_layer(const float* xin, bool first,
                          const float* W, const float* as, const float* ad, const float* b,
                          const int* gsrc, const int* gdst) {
    zero_scratch<<<(NN * 64 + 255) / 256, 256>>>();
    if (first) node_transform<true><<<(NN + 3) / 4, 256>>>(xin, W, as, ad);
    else       node_transform<false><<<(NN + 3) / 4, 256>>>(xin, W, as, ad);
    edge_alpha_max<<<(EG + 255) / 256, 256>>>(gsrc, gdst);
    decode_amax<<<(NN + 255) / 256, 256>>>();
    edge_exp_denom<<<(EG + 255) / 256, 256>>>(gdst);
    edge_scatter<<<((size_t)EG * 32 + 255) / 256, 256>>>(gsrc, gdst);
    finalize_node<<<(NN * 64 + 255) / 256, 256>>>(b);
}

extern "C" void kernel_launch(void* const* d_in, const int* in_sizes, int n_in,
                              void* d_out, int out_size) {
    const float* pos   = (const float*)d_in[0];
    const int*   eidx  = (const int*)d_in[1];
    const int*   geidx = (const int*)d_in[2];
    const float* eattr = (const float*)d_in[3];
    const float* W0    = (const float*)d_in[4];
    const float* as0   = (const float*)d_in[5];
    const float* ad0   = (const float*)d_in[6];
    const float* b0    = (const float*)d_in[7];
    const float* W1    = (const float*)d_in[8];
    const float* as1   = (const float*)d_in[9];
    const float* ad1   = (const float*)d_in[10];
    const float* b1    = (const float*)d_in[11];
    const float* Wm1   = (const float*)d_in[12];
    const float* bm1   = (const float*)d_in[13];
    const float* Wm2   = (const float*)d_in[14];
    const float* bm2   = (const float*)d_in[15];
    float* out = (float*)d_out;

    const int* gsrc = geidx;
    const int* gdst = geidx + EG;
    const int* esrc = eidx;
    const int* edst = eidx + EE;

    run_gat_layer(pos, true,  W0, as0, ad0, b0, gsrc, gdst);
    run_gat_layer(nullptr, false, W1, as1, ad1, b1, gsrc, gdst);

    dim3 ggrid(17, (NN + 63) / 64);
    gemm_y<<<ggrid, 256>>>(Wm1);

    edge_mlp<<<((size_t)EE * 32 + 255) / 256, 256>>>(esrc, edst, eattr, Wm1, bm1, Wm2, bm2, out);
}